// round 1
// baseline (speedup 1.0000x reference)
#include <cuda_runtime.h>
#include <cuda_bf16.h>
#include <cstdint>

// Problem constants
#define BB 1024
#define TT 128
#define NN 128
#define MM 256
#define PP 256

// ---------------- scratch (static device globals; no allocation) -------------
__device__ float g_UeT[(size_t)BB * TT * NN];   // [b][s][n]  (s = time index of Ue rows)
__device__ float g_H  [(size_t)BB * TT * MM];   // [b][t][m]
__device__ float g_UHT[(size_t)BB * MM * TT];   // [b][u][t]
__device__ float g_h[BB * MM];
__device__ float g_c[BB * MM];
__device__ float g_d[BB * PP];
__device__ float g_s[BB * PP];
__device__ float g_xt[BB * NN];
__device__ float g_gates[BB * 4 * MM];          // 1024 x 1024
__device__ float g_yt[BB];
__device__ float g_ctx[BB * MM];

// ---------------- math helpers ----------------------------------------------
__device__ __forceinline__ float ftanh(float x) {
    x = fminf(fmaxf(x, -15.f), 15.f);
    float e = __expf(2.f * x);
    return __fdividef(e - 1.f, e + 1.f);
}
__device__ __forceinline__ float fsig(float x) {
    x = fminf(fmaxf(x, -30.f), 30.f);
    return __fdividef(1.f, 1.f + __expf(-x));
}

// ---------------- init -------------------------------------------------------
__global__ void zero_states_kernel() {
    int idx = blockIdx.x * blockDim.x + threadIdx.x;
    if (idx < BB * MM) {
        g_h[idx] = 0.f; g_c[idx] = 0.f; g_d[idx] = 0.f; g_s[idx] = 0.f;
    }
}

// ---------------- precompute UeT[b][s][n] = sum_t Ue[s][t] * enc[b][t][n] ----
// grid: (N/64, T/64, B), 256 threads, 4x4 micro
__global__ __launch_bounds__(256) void ue_pre_kernel(
    const float* __restrict__ enc_data, const float* __restrict__ Ue)
{
    __shared__ float As[16][65];   // [k][s]
    __shared__ float Bs[16][65];   // [k][n]
    const int n0 = blockIdx.x * 64;
    const int s0 = blockIdx.y * 64;
    const int b  = blockIdx.z;
    const int tid = threadIdx.x;
    const int tx = tid & 15, ty = tid >> 4;
    float acc[4][4];
#pragma unroll
    for (int i = 0; i < 4; i++)
#pragma unroll
        for (int j = 0; j < 4; j++) acc[i][j] = 0.f;

    for (int k0 = 0; k0 < TT; k0 += 16) {
#pragma unroll
        for (int i = 0; i < 4; i++) {
            int idx = tid + i * 256;
            int m = idx >> 4, k = idx & 15;
            As[k][m] = Ue[(s0 + m) * TT + (k0 + k)];
        }
#pragma unroll
        for (int i = 0; i < 4; i++) {
            int idx = tid + i * 256;
            int nn2 = idx & 63, k = idx >> 6;
            Bs[k][nn2] = enc_data[((size_t)b * TT + (k0 + k)) * NN + n0 + nn2];
        }
        __syncthreads();
#pragma unroll
        for (int kk = 0; kk < 16; kk++) {
            float a[4], bv[4];
#pragma unroll
            for (int i = 0; i < 4; i++) a[i] = As[kk][ty * 4 + i];
#pragma unroll
            for (int j = 0; j < 4; j++) bv[j] = Bs[kk][tx * 4 + j];
#pragma unroll
            for (int i = 0; i < 4; i++)
#pragma unroll
                for (int j = 0; j < 4; j++) acc[i][j] += a[i] * bv[j];
        }
        __syncthreads();
    }
#pragma unroll
    for (int i = 0; i < 4; i++) {
        int s = s0 + ty * 4 + i;
#pragma unroll
        for (int j = 0; j < 4; j++) {
            int n = n0 + tx * 4 + j;
            g_UeT[((size_t)b * TT + s) * NN + n] = acc[i][j];
        }
    }
}

// ---------------- precompute UHT[b][u][t] = sum_m Ud[u][m] * H[b][t][m] ------
// grid: (T/64, M/64, B)
__global__ __launch_bounds__(256) void uh_pre_kernel(const float* __restrict__ Ud)
{
    __shared__ float As[16][65];   // [k][u]
    __shared__ float Bs[16][65];   // [k][t]
    const int t0 = blockIdx.x * 64;
    const int u0 = blockIdx.y * 64;
    const int b  = blockIdx.z;
    const int tid = threadIdx.x;
    const int tx = tid & 15, ty = tid >> 4;
    float acc[4][4];
#pragma unroll
    for (int i = 0; i < 4; i++)
#pragma unroll
        for (int j = 0; j < 4; j++) acc[i][j] = 0.f;

    for (int k0 = 0; k0 < MM; k0 += 16) {
#pragma unroll
        for (int i = 0; i < 4; i++) {
            int idx = tid + i * 256;
            int m = idx >> 4, k = idx & 15;
            As[k][m] = Ud[(u0 + m) * MM + (k0 + k)];
            Bs[k][m] = g_H[((size_t)b * TT + (t0 + m)) * MM + (k0 + k)];
        }
        __syncthreads();
#pragma unroll
        for (int kk = 0; kk < 16; kk++) {
            float a[4], bv[4];
#pragma unroll
            for (int i = 0; i < 4; i++) a[i] = As[kk][ty * 4 + i];
#pragma unroll
            for (int j = 0; j < 4; j++) bv[j] = Bs[kk][tx * 4 + j];
#pragma unroll
            for (int i = 0; i < 4; i++)
#pragma unroll
                for (int j = 0; j < 4; j++) acc[i][j] += a[i] * bv[j];
        }
        __syncthreads();
    }
#pragma unroll
    for (int i = 0; i < 4; i++) {
        int u = u0 + ty * 4 + i;
#pragma unroll
        for (int j = 0; j < 4; j++) {
            int t = t0 + tx * 4 + j;
            g_UHT[((size_t)b * MM + u) * TT + t] = acc[i][j];
        }
    }
}

// ---------------- encoder attention (one block per batch, 128 threads) -------
__global__ __launch_bounds__(128) void enc_attn_kernel(
    const float* __restrict__ enc_data, const float* __restrict__ We,
    const float* __restrict__ ve, int t)
{
    const int b = blockIdx.x;
    const int tid = threadIdx.x;   // 128
    __shared__ float sh_h[MM], sh_c[MM], sh_wq[TT], sh_ve[TT], sh_red[TT];

    sh_h[tid]       = g_h[b * MM + tid];
    sh_h[tid + 128] = g_h[b * MM + tid + 128];
    sh_c[tid]       = g_c[b * MM + tid];
    sh_c[tid + 128] = g_c[b * MM + tid + 128];
    sh_ve[tid] = ve[tid];
    __syncthreads();

    // wq[s] = [h,c] . We[s,:]
    {
        float acc = 0.f;
        const float* wrow = We + tid * (2 * MM);
#pragma unroll 8
        for (int k = 0; k < MM; k++) acc += sh_h[k] * wrow[k];
#pragma unroll 8
        for (int k = 0; k < MM; k++) acc += sh_c[k] * wrow[MM + k];
        sh_wq[tid] = acc;
    }
    __syncthreads();

    // score[n=tid] = sum_s tanh(wq[s] + UeT[b][s][n]) * ve[s]
    float sc = 0.f;
    {
        const float* ue = g_UeT + (size_t)b * TT * NN + tid;
#pragma unroll 4
        for (int s = 0; s < TT; s++)
            sc += ftanh(sh_wq[s] + ue[(size_t)s * NN]) * sh_ve[s];
    }
    // softmax over n (128 threads)
    sh_red[tid] = sc;
    __syncthreads();
    for (int off = 64; off > 0; off >>= 1) {
        if (tid < off) sh_red[tid] = fmaxf(sh_red[tid], sh_red[tid + off]);
        __syncthreads();
    }
    float mx = sh_red[0];
    __syncthreads();
    float e = __expf(sc - mx);
    sh_red[tid] = e;
    __syncthreads();
    for (int off = 64; off > 0; off >>= 1) {
        if (tid < off) sh_red[tid] += sh_red[tid + off];
        __syncthreads();
    }
    float alpha = __fdividef(e, sh_red[0]);
    g_xt[b * NN + tid] = alpha * enc_data[((size_t)b * TT + t) * NN + tid];
}

// ---------------- encoder LSTM gates GEMM ------------------------------------
// gates[b][j] = xt . Wih[j,:] + h . Whh[j,:] + bih[j] + bhh[j]
// grid (16,16), 256 threads, 64x64 tile, 4x4 micro
__global__ __launch_bounds__(256) void enc_gates_kernel(
    const float* __restrict__ Wih, const float* __restrict__ Whh,
    const float* __restrict__ bih, const float* __restrict__ bhh)
{
    __shared__ float As[16][65];
    __shared__ float Bs[16][65];
    const int bn = blockIdx.x, bm = blockIdx.y;
    const int tid = threadIdx.x;
    const int tx = tid & 15, ty = tid >> 4;
    float acc[4][4];
#pragma unroll
    for (int i = 0; i < 4; i++)
#pragma unroll
        for (int j = 0; j < 4; j++) acc[i][j] = 0.f;

    // phase 1: K = NN = 128 (xt, Wih)
    for (int k0 = 0; k0 < NN; k0 += 16) {
#pragma unroll
        for (int i = 0; i < 4; i++) {
            int idx = tid + i * 256;
            int m = idx >> 4, k = idx & 15;
            As[k][m] = g_xt[(bm * 64 + m) * NN + (k0 + k)];
            Bs[k][m] = Wih[(bn * 64 + m) * NN + (k0 + k)];
        }
        __syncthreads();
#pragma unroll
        for (int kk = 0; kk < 16; kk++) {
            float a[4], bv[4];
#pragma unroll
            for (int i = 0; i < 4; i++) a[i] = As[kk][ty * 4 + i];
#pragma unroll
            for (int j = 0; j < 4; j++) bv[j] = Bs[kk][tx * 4 + j];
#pragma unroll
            for (int i = 0; i < 4; i++)
#pragma unroll
                for (int j = 0; j < 4; j++) acc[i][j] += a[i] * bv[j];
        }
        __syncthreads();
    }
    // phase 2: K = MM = 256 (h, Whh)
    for (int k0 = 0; k0 < MM; k0 += 16) {
#pragma unroll
        for (int i = 0; i < 4; i++) {
            int idx = tid + i * 256;
            int m = idx >> 4, k = idx & 15;
            As[k][m] = g_h[(bm * 64 + m) * MM + (k0 + k)];
            Bs[k][m] = Whh[(bn * 64 + m) * MM + (k0 + k)];
        }
        __syncthreads();
#pragma unroll
        for (int kk = 0; kk < 16; kk++) {
            float a[4], bv[4];
#pragma unroll
            for (int i = 0; i < 4; i++) a[i] = As[kk][ty * 4 + i];
#pragma unroll
            for (int j = 0; j < 4; j++) bv[j] = Bs[kk][tx * 4 + j];
#pragma unroll
            for (int i = 0; i < 4; i++)
#pragma unroll
                for (int j = 0; j < 4; j++) acc[i][j] += a[i] * bv[j];
        }
        __syncthreads();
    }
#pragma unroll
    for (int i = 0; i < 4; i++) {
        int row = bm * 64 + ty * 4 + i;
#pragma unroll
        for (int j = 0; j < 4; j++) {
            int col = bn * 64 + tx * 4 + j;
            g_gates[row * 1024 + col] = acc[i][j] + bih[col] + bhh[col];
        }
    }
}

// ---------------- encoder LSTM activation ------------------------------------
__global__ __launch_bounds__(256) void enc_act_kernel(int t)
{
    int idx = blockIdx.x * blockDim.x + threadIdx.x;  // B*M
    int b = idx >> 8, j = idx & 255;
    const float* g = g_gates + b * 1024;
    float gi = g[j], gf = g[j + 256], gg = g[j + 512], go = g[j + 768];
    float c = g_c[idx];
    float cn = fsig(gf) * c + fsig(gi) * ftanh(gg);
    float hn = fsig(go) * ftanh(cn);
    g_c[idx] = cn;
    g_h[idx] = hn;
    g_H[((size_t)b * TT + t) * MM + j] = hn;
}

// ---------------- decoder attention (one block per batch, 256 threads) -------
// if write_ctx: store ctx to g_ctx; else compute y_tilde into g_yt
__global__ __launch_bounds__(256) void dec_attn_kernel(
    const float* __restrict__ dec_data, const float* __restrict__ Wd,
    const float* __restrict__ vd, const float* __restrict__ wt_w,
    const float* __restrict__ wt_b, int step, int write_ctx)
{
    const int b = blockIdx.x;
    const int tid = threadIdx.x;  // 256
    __shared__ float sh_d[PP], sh_s[PP], sh_wq[MM], sh_vd[MM];
    __shared__ float sh_beta[TT], sh_red[256];

    sh_d[tid] = g_d[b * PP + tid];
    sh_s[tid] = g_s[b * PP + tid];
    sh_vd[tid] = vd[tid];
    __syncthreads();

    // wq[u] = [d,s] . Wd[u,:]
    {
        float acc = 0.f;
        const float* wrow = Wd + tid * (2 * PP);
#pragma unroll 8
        for (int k = 0; k < PP; k++) acc += sh_d[k] * wrow[k];
#pragma unroll 8
        for (int k = 0; k < PP; k++) acc += sh_s[k] * wrow[PP + k];
        sh_wq[tid] = acc;
    }
    __syncthreads();

    // score[t] for tid < 128
    float sc = 0.f;
    if (tid < TT) {
        const float* uh = g_UHT + (size_t)b * MM * TT + tid;
#pragma unroll 4
        for (int u = 0; u < MM; u++)
            sc += ftanh(sh_wq[u] + uh[(size_t)u * TT]) * sh_vd[u];
    }
    sh_red[tid] = (tid < TT) ? sc : -1e30f;
    __syncthreads();
    for (int off = 128; off > 0; off >>= 1) {
        if (tid < off) sh_red[tid] = fmaxf(sh_red[tid], sh_red[tid + off]);
        __syncthreads();
    }
    float mx = sh_red[0];
    __syncthreads();
    float e = (tid < TT) ? __expf(sc - mx) : 0.f;
    sh_red[tid] = e;
    __syncthreads();
    for (int off = 128; off > 0; off >>= 1) {
        if (tid < off) sh_red[tid] += sh_red[tid + off];
        __syncthreads();
    }
    float ssum = sh_red[0];
    __syncthreads();
    if (tid < TT) sh_beta[tid] = __fdividef(e, ssum);
    __syncthreads();

    // ctx[m=tid] = sum_t beta[t] * H[b][t][m]
    float ctx = 0.f;
    {
        const float* hrow = g_H + (size_t)b * TT * MM + tid;
#pragma unroll 4
        for (int t2 = 0; t2 < TT; t2++) ctx += sh_beta[t2] * hrow[(size_t)t2 * MM];
    }

    if (write_ctx) {
        g_ctx[b * MM + tid] = ctx;
        return;
    }
    // y_tilde = y * wt_w[0] + sum_m ctx[m]*wt_w[1+m] + wt_b
    sh_red[tid] = ctx * wt_w[1 + tid];
    __syncthreads();
    for (int off = 128; off > 0; off >>= 1) {
        if (tid < off) sh_red[tid] += sh_red[tid + off];
        __syncthreads();
    }
    if (tid == 0) {
        float y = dec_data[(size_t)b * TT + step];
        g_yt[b] = sh_red[0] + y * wt_w[0] + wt_b[0];
    }
}

// ---------------- decoder LSTM gates GEMM ------------------------------------
// gates[b][j] = yt[b]*Wih[j] + d . Whh[j,:] + bih[j] + bhh[j]
__global__ __launch_bounds__(256) void dec_gates_kernel(
    const float* __restrict__ Wih, const float* __restrict__ Whh,
    const float* __restrict__ bih, const float* __restrict__ bhh)
{
    __shared__ float As[16][65];
    __shared__ float Bs[16][65];
    const int bn = blockIdx.x, bm = blockIdx.y;
    const int tid = threadIdx.x;
    const int tx = tid & 15, ty = tid >> 4;
    float acc[4][4];
#pragma unroll
    for (int i = 0; i < 4; i++)
#pragma unroll
        for (int j = 0; j < 4; j++) acc[i][j] = 0.f;

    for (int k0 = 0; k0 < PP; k0 += 16) {
#pragma unroll
        for (int i = 0; i < 4; i++) {
            int idx = tid + i * 256;
            int m = idx >> 4, k = idx & 15;
            As[k][m] = g_d[(bm * 64 + m) * PP + (k0 + k)];
            Bs[k][m] = Whh[(bn * 64 + m) * PP + (k0 + k)];
        }
        __syncthreads();
#pragma unroll
        for (int kk = 0; kk < 16; kk++) {
            float a[4], bv[4];
#pragma unroll
            for (int i = 0; i < 4; i++) a[i] = As[kk][ty * 4 + i];
#pragma unroll
            for (int j = 0; j < 4; j++) bv[j] = Bs[kk][tx * 4 + j];
#pragma unroll
            for (int i = 0; i < 4; i++)
#pragma unroll
                for (int j = 0; j < 4; j++) acc[i][j] += a[i] * bv[j];
        }
        __syncthreads();
    }
#pragma unroll
    for (int i = 0; i < 4; i++) {
        int row = bm * 64 + ty * 4 + i;
        float yt = g_yt[row];
#pragma unroll
        for (int j = 0; j < 4; j++) {
            int col = bn * 64 + tx * 4 + j;
            g_gates[row * 1024 + col] = acc[i][j] + yt * Wih[col] + bih[col] + bhh[col];
        }
    }
}

// ---------------- decoder LSTM activation ------------------------------------
__global__ __launch_bounds__(256) void dec_act_kernel()
{
    int idx = blockIdx.x * blockDim.x + threadIdx.x;  // B*P
    int b = idx >> 8, j = idx & 255;
    const float* g = g_gates + b * 1024;
    float gi = g[j], gf = g[j + 256], gg = g[j + 512], go = g[j + 768];
    float s = g_s[idx];
    float sn = fsig(gf) * s + fsig(gi) * ftanh(gg);
    float dn = fsig(go) * ftanh(sn);
    g_s[idx] = sn;
    g_d[idx] = dn;
}

// ---------------- final head: out = relu([d,ctx] @ l1^T + b1) @ l2^T + b2 ----
__global__ __launch_bounds__(256) void head_kernel(
    const float* __restrict__ l1_w, const float* __restrict__ l1_b,
    const float* __restrict__ l2_w, const float* __restrict__ l2_b,
    float* __restrict__ out)
{
    const int b = blockIdx.x;
    const int tid = threadIdx.x;  // 256
    __shared__ float v[512];
    __shared__ float r[256];
    v[tid] = g_d[b * PP + tid];
    v[256 + tid] = g_ctx[b * MM + tid];
    __syncthreads();
    float a = l1_b[tid];
    const float* w = l1_w + tid * 512;
#pragma unroll 8
    for (int k = 0; k < 512; k++) a += v[k] * w[k];
    a = fmaxf(a, 0.f);
    r[tid] = a * l2_w[tid];
    __syncthreads();
    for (int off = 128; off > 0; off >>= 1) {
        if (tid < off) r[tid] += r[tid + off];
        __syncthreads();
    }
    if (tid == 0) out[b] = r[0] + l2_b[0];
}

// ---------------- launch -----------------------------------------------------
extern "C" void kernel_launch(void* const* d_in, const int* in_sizes, int n_in,
                              void* d_out, int out_size)
{
    const float* enc_data = (const float*)d_in[0];
    const float* dec_data = (const float*)d_in[1];
    const float* enc_Wih  = (const float*)d_in[2];
    const float* enc_Whh  = (const float*)d_in[3];
    const float* enc_bih  = (const float*)d_in[4];
    const float* enc_bhh  = (const float*)d_in[5];
    const float* We       = (const float*)d_in[6];
    const float* Ue       = (const float*)d_in[7];
    const float* ve       = (const float*)d_in[8];
    const float* Wd       = (const float*)d_in[9];
    const float* Ud       = (const float*)d_in[10];
    const float* vd       = (const float*)d_in[11];
    const float* wt_w     = (const float*)d_in[12];
    const float* wt_b     = (const float*)d_in[13];
    const float* dec_Wih  = (const float*)d_in[14];
    const float* dec_Whh  = (const float*)d_in[15];
    const float* dec_bih  = (const float*)d_in[16];
    const float* dec_bhh  = (const float*)d_in[17];
    const float* l1_w     = (const float*)d_in[18];
    const float* l1_b     = (const float*)d_in[19];
    const float* l2_w     = (const float*)d_in[20];
    const float* l2_b     = (const float*)d_in[21];
    float* out = (float*)d_out;

    zero_states_kernel<<<(BB * MM + 255) / 256, 256>>>();
    ue_pre_kernel<<<dim3(NN / 64, TT / 64, BB), 256>>>(enc_data, Ue);

    for (int t = 0; t < TT; t++) {
        enc_attn_kernel<<<BB, 128>>>(enc_data, We, ve, t);
        enc_gates_kernel<<<dim3(16, 16), 256>>>(enc_Wih, enc_Whh, enc_bih, enc_bhh);
        enc_act_kernel<<<(BB * MM) / 256, 256>>>(t);
    }

    uh_pre_kernel<<<dim3(TT / 64, MM / 64, BB), 256>>>(Ud);

    for (int step = 0; step < TT - 1; step++) {
        dec_attn_kernel<<<BB, 256>>>(dec_data, Wd, vd, wt_w, wt_b, step, 0);
        dec_gates_kernel<<<dim3(16, 16), 256>>>(dec_Wih, dec_Whh, dec_bih, dec_bhh);
        dec_act_kernel<<<(BB * PP) / 256, 256>>>();
    }

    dec_attn_kernel<<<BB, 256>>>(dec_data, Wd, vd, wt_w, wt_b, 0, 1);
    head_kernel<<<BB, 256>>>(l1_w, l1_b, l2_w, l2_b, out);
}

// round 5
// speedup vs baseline: 3.4454x; 3.4454x over previous
#include <cuda_runtime.h>
#include <cuda_bf16.h>
#include <cstdint>

// Problem constants
#define BB 1024
#define TT 128
#define NN 128
#define MM 256
#define PP 256

// ---------------- scratch (static device globals; no allocation) -------------
__device__ float g_UeT[(size_t)BB * TT * NN];   // [b][s][n]
__device__ float g_H  [(size_t)BB * TT * MM];   // [b][t][m]
__device__ float g_UHT[(size_t)BB * MM * TT];   // [b][u][t]
__device__ float g_h[2][BB * MM];               // parity double-buffered
__device__ float g_c[2][BB * MM];
__device__ float g_d[2][BB * PP];
__device__ float g_s[2][BB * PP];
__device__ float g_xt[BB * NN];
__device__ float g_yt[BB];
__device__ float g_wqe[BB * TT];                // encoder attn query proj
__device__ float g_wqd[BB * MM];                // decoder attn query proj

// ---------------- math helpers ----------------------------------------------
__device__ __forceinline__ float ftanh(float x) {
    x = fminf(fmaxf(x, -15.f), 15.f);
    float e = __expf(2.f * x);
    return __fdividef(e - 1.f, e + 1.f);
}
__device__ __forceinline__ float fsig(float x) {
    x = fminf(fmaxf(x, -30.f), 30.f);
    return __fdividef(1.f, 1.f + __expf(-x));
}

// ---------------- precompute UeT[b][s][n] = sum_t Ue[s][t] * enc[b][t][n] ----
// grid (N/64=2, T/64=2, B); blocks with (x==0,y==0) also zero the LSTM states.
__global__ __launch_bounds__(256) void ue_pre_kernel(
    const float* __restrict__ enc_data, const float* __restrict__ Ue)
{
    __shared__ float As[16][65];
    __shared__ float Bs[16][65];
    const int n0 = blockIdx.x * 64;
    const int s0 = blockIdx.y * 64;
    const int b  = blockIdx.z;
    const int tid = threadIdx.x;
    const int tx = tid & 15, ty = tid >> 4;

    if (blockIdx.x == 0 && blockIdx.y == 0) {
        int idx = b * 256 + tid;   // MM == PP == 256
        g_h[0][idx] = 0.f; g_h[1][idx] = 0.f;
        g_c[0][idx] = 0.f; g_c[1][idx] = 0.f;
        g_d[0][idx] = 0.f; g_d[1][idx] = 0.f;
        g_s[0][idx] = 0.f; g_s[1][idx] = 0.f;
    }

    float acc[4][4];
#pragma unroll
    for (int i = 0; i < 4; i++)
#pragma unroll
        for (int j = 0; j < 4; j++) acc[i][j] = 0.f;

    for (int k0 = 0; k0 < TT; k0 += 16) {
#pragma unroll
        for (int i = 0; i < 4; i++) {
            int idx = tid + i * 256;
            int m = idx >> 4, k = idx & 15;
            As[k][m] = Ue[(s0 + m) * TT + (k0 + k)];
        }
#pragma unroll
        for (int i = 0; i < 4; i++) {
            int idx = tid + i * 256;
            int nn2 = idx & 63, k = idx >> 6;
            Bs[k][nn2] = enc_data[((size_t)b * TT + (k0 + k)) * NN + n0 + nn2];
        }
        __syncthreads();
#pragma unroll
        for (int kk = 0; kk < 16; kk++) {
            float a[4], bv[4];
#pragma unroll
            for (int i = 0; i < 4; i++) a[i] = As[kk][ty * 4 + i];
#pragma unroll
            for (int j = 0; j < 4; j++) bv[j] = Bs[kk][tx * 4 + j];
#pragma unroll
            for (int i = 0; i < 4; i++)
#pragma unroll
                for (int j = 0; j < 4; j++) acc[i][j] += a[i] * bv[j];
        }
        __syncthreads();
    }
#pragma unroll
    for (int i = 0; i < 4; i++) {
        int s = s0 + ty * 4 + i;
#pragma unroll
        for (int j = 0; j < 4; j++) {
            int n = n0 + tx * 4 + j;
            g_UeT[((size_t)b * TT + s) * NN + n] = acc[i][j];
        }
    }
}

// ---------------- precompute UHT[b][u][t] = sum_m Ud[u][m] * H[b][t][m] ------
__global__ __launch_bounds__(256) void uh_pre_kernel(const float* __restrict__ Ud)
{
    __shared__ float As[16][65];
    __shared__ float Bs[16][65];
    const int t0 = blockIdx.x * 64;
    const int u0 = blockIdx.y * 64;
    const int b  = blockIdx.z;
    const int tid = threadIdx.x;
    const int tx = tid & 15, ty = tid >> 4;
    float acc[4][4];
#pragma unroll
    for (int i = 0; i < 4; i++)
#pragma unroll
        for (int j = 0; j < 4; j++) acc[i][j] = 0.f;

    for (int k0 = 0; k0 < MM; k0 += 16) {
#pragma unroll
        for (int i = 0; i < 4; i++) {
            int idx = tid + i * 256;
            int m = idx >> 4, k = idx & 15;
            As[k][m] = Ud[(u0 + m) * MM + (k0 + k)];
            Bs[k][m] = g_H[((size_t)b * TT + (t0 + m)) * MM + (k0 + k)];
        }
        __syncthreads();
#pragma unroll
        for (int kk = 0; kk < 16; kk++) {
            float a[4], bv[4];
#pragma unroll
            for (int i = 0; i < 4; i++) a[i] = As[kk][ty * 4 + i];
#pragma unroll
            for (int j = 0; j < 4; j++) bv[j] = Bs[kk][tx * 4 + j];
#pragma unroll
            for (int i = 0; i < 4; i++)
#pragma unroll
                for (int j = 0; j < 4; j++) acc[i][j] += a[i] * bv[j];
        }
        __syncthreads();
    }
#pragma unroll
    for (int i = 0; i < 4; i++) {
        int u = u0 + ty * 4 + i;
#pragma unroll
        for (int j = 0; j < 4; j++) {
            int t = t0 + tx * 4 + j;
            g_UHT[((size_t)b * MM + u) * TT + t] = acc[i][j];
        }
    }
}

// ---------------- encoder wq GEMM: wq[b][s] = [h|c] . We[s,:] ----------------
__global__ __launch_bounds__(256) void enc_wq_kernel(const float* __restrict__ We, int p)
{
    __shared__ float As[16][65];
    __shared__ float Bs[16][65];
    const int s0 = blockIdx.x * 64;
    const int b0 = blockIdx.y * 64;
    const int tid = threadIdx.x;
    const int tx = tid & 15, ty = tid >> 4;
    float acc[4][4];
#pragma unroll
    for (int i = 0; i < 4; i++)
#pragma unroll
        for (int j = 0; j < 4; j++) acc[i][j] = 0.f;

#pragma unroll
    for (int phase = 0; phase < 2; phase++) {
        const float* q = phase ? g_c[p] : g_h[p];
        for (int k0 = 0; k0 < MM; k0 += 16) {
#pragma unroll
            for (int i = 0; i < 4; i++) {
                int idx = tid + i * 256;
                int m = idx >> 4, k = idx & 15;
                As[k][m] = q[(b0 + m) * MM + (k0 + k)];
                Bs[k][m] = We[(s0 + m) * (2 * MM) + phase * MM + (k0 + k)];
            }
            __syncthreads();
#pragma unroll
            for (int kk = 0; kk < 16; kk++) {
                float a[4], bv[4];
#pragma unroll
                for (int i = 0; i < 4; i++) a[i] = As[kk][ty * 4 + i];
#pragma unroll
                for (int j = 0; j < 4; j++) bv[j] = Bs[kk][tx * 4 + j];
#pragma unroll
                for (int i = 0; i < 4; i++)
#pragma unroll
                    for (int j = 0; j < 4; j++) acc[i][j] += a[i] * bv[j];
            }
            __syncthreads();
        }
    }
#pragma unroll
    for (int i = 0; i < 4; i++) {
        int b = b0 + ty * 4 + i;
#pragma unroll
        for (int j = 0; j < 4; j++) {
            int s = s0 + tx * 4 + j;
            g_wqe[b * TT + s] = acc[i][j];
        }
    }
}

// ---------------- decoder wq GEMM: wq[b][u] = [d|s] . Wd[u,:] ----------------
__global__ __launch_bounds__(256) void dec_wq_kernel(const float* __restrict__ Wd, int p)
{
    __shared__ float As[16][65];
    __shared__ float Bs[16][65];
    const int u0 = blockIdx.x * 64;
    const int b0 = blockIdx.y * 64;
    const int tid = threadIdx.x;
    const int tx = tid & 15, ty = tid >> 4;
    float acc[4][4];
#pragma unroll
    for (int i = 0; i < 4; i++)
#pragma unroll
        for (int j = 0; j < 4; j++) acc[i][j] = 0.f;

#pragma unroll
    for (int phase = 0; phase < 2; phase++) {
        const float* q = phase ? g_s[p] : g_d[p];
        for (int k0 = 0; k0 < PP; k0 += 16) {
#pragma unroll
            for (int i = 0; i < 4; i++) {
                int idx = tid + i * 256;
                int m = idx >> 4, k = idx & 15;
                As[k][m] = q[(b0 + m) * PP + (k0 + k)];
                Bs[k][m] = Wd[(u0 + m) * (2 * PP) + phase * PP + (k0 + k)];
            }
            __syncthreads();
#pragma unroll
            for (int kk = 0; kk < 16; kk++) {
                float a[4], bv[4];
#pragma unroll
                for (int i = 0; i < 4; i++) a[i] = As[kk][ty * 4 + i];
#pragma unroll
                for (int j = 0; j < 4; j++) bv[j] = Bs[kk][tx * 4 + j];
#pragma unroll
                for (int i = 0; i < 4; i++)
#pragma unroll
                    for (int j = 0; j < 4; j++) acc[i][j] += a[i] * bv[j];
            }
            __syncthreads();
        }
    }
#pragma unroll
    for (int i = 0; i < 4; i++) {
        int b = b0 + ty * 4 + i;
#pragma unroll
        for (int j = 0; j < 4; j++) {
            int u = u0 + tx * 4 + j;
            g_wqd[b * MM + u] = acc[i][j];
        }
    }
}

// ---------------- encoder attention (one block per batch, 128 threads) -------
__global__ __launch_bounds__(128) void enc_attn_kernel(
    const float* __restrict__ enc_data, const float* __restrict__ ve, int t)
{
    const int b = blockIdx.x;
    const int tid = threadIdx.x;   // 128
    __shared__ float sh_wq[TT], sh_ve[TT], sh_red[TT];

    sh_wq[tid] = g_wqe[b * TT + tid];
    sh_ve[tid] = ve[tid];
    __syncthreads();

    float sc = 0.f;
    {
        const float* ue = g_UeT + (size_t)b * TT * NN + tid;
#pragma unroll 4
        for (int s = 0; s < TT; s++)
            sc += ftanh(sh_wq[s] + ue[(size_t)s * NN]) * sh_ve[s];
    }
    sh_red[tid] = sc;
    __syncthreads();
    for (int off = 64; off > 0; off >>= 1) {
        if (tid < off) sh_red[tid] = fmaxf(sh_red[tid], sh_red[tid + off]);
        __syncthreads();
    }
    float mx = sh_red[0];
    __syncthreads();
    float e = __expf(sc - mx);
    sh_red[tid] = e;
    __syncthreads();
    for (int off = 64; off > 0; off >>= 1) {
        if (tid < off) sh_red[tid] += sh_red[tid + off];
        __syncthreads();
    }
    float alpha = __fdividef(e, sh_red[0]);
    g_xt[b * NN + tid] = alpha * enc_data[((size_t)b * TT + t) * NN + tid];
}

// ---------------- encoder LSTM gates GEMM + fused activation -----------------
// grid (16 j-tiles, 16 b-tiles), 256 threads. Block computes 64 batches x
// 16 hidden x 4 gates (cols gate*256 + j0 + jj), then applies LSTM act inline.
__global__ __launch_bounds__(256) void enc_gates_act_kernel(
    const float* __restrict__ Wih, const float* __restrict__ Whh,
    const float* __restrict__ bih, const float* __restrict__ bhh,
    int t, int p)
{
    __shared__ float As[16][65];
    __shared__ float Bs[16][68];
    __shared__ float Sg[64][68];
    const int j0 = blockIdx.x * 16;
    const int b0 = blockIdx.y * 64;
    const int tid = threadIdx.x;
    const int tx = tid & 15, ty = tid >> 4;
    float acc[4][4];
#pragma unroll
    for (int i = 0; i < 4; i++)
#pragma unroll
        for (int j = 0; j < 4; j++) acc[i][j] = 0.f;

    const float* h_in = g_h[p];
    const float* c_in = g_c[p];
    float* h_out = g_h[p ^ 1];
    float* c_out = g_c[p ^ 1];

    // phase 1: xt @ Wih^T  (K = NN = 128)
    for (int k0 = 0; k0 < NN; k0 += 16) {
#pragma unroll
        for (int i = 0; i < 4; i++) {
            int idx = tid + i * 256;
            int c = idx >> 4, k = idx & 15;
            As[k][c] = g_xt[(b0 + c) * NN + (k0 + k)];
            int gate = c >> 4, jj = c & 15;
            Bs[k][c] = Wih[(gate * 256 + j0 + jj) * NN + (k0 + k)];
        }
        __syncthreads();
#pragma unroll
        for (int kk = 0; kk < 16; kk++) {
            float a[4], bv[4];
#pragma unroll
            for (int i = 0; i < 4; i++) a[i] = As[kk][ty * 4 + i];
#pragma unroll
            for (int j = 0; j < 4; j++) bv[j] = Bs[kk][tx * 4 + j];
#pragma unroll
            for (int i = 0; i < 4; i++)
#pragma unroll
                for (int j = 0; j < 4; j++) acc[i][j] += a[i] * bv[j];
        }
        __syncthreads();
    }
    // phase 2: h @ Whh^T  (K = MM = 256)
    for (int k0 = 0; k0 < MM; k0 += 16) {
#pragma unroll
        for (int i = 0; i < 4; i++) {
            int idx = tid + i * 256;
            int c = idx >> 4, k = idx & 15;
            As[k][c] = h_in[(b0 + c) * MM + (k0 + k)];
            int gate = c >> 4, jj = c & 15;
            Bs[k][c] = Whh[(gate * 256 + j0 + jj) * MM + (k0 + k)];
        }
        __syncthreads();
#pragma unroll
        for (int kk = 0; kk < 16; kk++) {
            float a[4], bv[4];
#pragma unroll
            for (int i = 0; i < 4; i++) a[i] = As[kk][ty * 4 + i];
#pragma unroll
            for (int j = 0; j < 4; j++) bv[j] = Bs[kk][tx * 4 + j];
#pragma unroll
            for (int i = 0; i < 4; i++)
#pragma unroll
                for (int j = 0; j < 4; j++) acc[i][j] += a[i] * bv[j];
        }
        __syncthreads();
    }
    // stash tile to smem for gate transpose
#pragma unroll
    for (int i = 0; i < 4; i++)
#pragma unroll
        for (int j = 0; j < 4; j++)
            Sg[ty * 4 + i][tx * 4 + j] = acc[i][j];
    __syncthreads();

    // activation: 64 rows x 16 jj = 1024 elems, 4 per thread
#pragma unroll
    for (int i = 0; i < 4; i++) {
        int idx = tid + i * 256;
        int r = idx >> 4, jj = idx & 15;
        int col0 = j0 + jj;
        float gi = Sg[r][jj]      + bih[col0]       + bhh[col0];
        float gf = Sg[r][16 + jj] + bih[256 + col0] + bhh[256 + col0];
        float gg = Sg[r][32 + jj] + bih[512 + col0] + bhh[512 + col0];
        float go = Sg[r][48 + jj] + bih[768 + col0] + bhh[768 + col0];
        int b = b0 + r;
        int sidx = b * MM + col0;
        float c_old = c_in[sidx];
        float cn = fsig(gf) * c_old + fsig(gi) * ftanh(gg);
        float hn = fsig(go) * ftanh(cn);
        c_out[sidx] = cn;
        h_out[sidx] = hn;
        g_H[((size_t)b * TT + t) * MM + col0] = hn;
    }
}

// ---------------- decoder attention (one block per batch, 256 threads) -------
// final==0: compute y_tilde into g_yt.  final==1: compute ctx and run the head.
__global__ __launch_bounds__(256) void dec_attn_kernel(
    const float* __restrict__ dec_data, const float* __restrict__ vd,
    const float* __restrict__ wt_w, const float* __restrict__ wt_b,
    int step, int final_mode, int p,
    const float* __restrict__ l1_w, const float* __restrict__ l1_b,
    const float* __restrict__ l2_w, const float* __restrict__ l2_b,
    float* __restrict__ out)
{
    const int b = blockIdx.x;
    const int tid = threadIdx.x;  // 256
    __shared__ float sh_wq[MM], sh_vd[MM];
    __shared__ float sh_beta[TT], sh_red[256];
    __shared__ float sh_v[512];

    sh_wq[tid] = g_wqd[b * MM + tid];
    sh_vd[tid] = vd[tid];
    __syncthreads();

    float sc = 0.f;
    if (tid < TT) {
        const float* uh = g_UHT + (size_t)b * MM * TT + tid;
#pragma unroll 4
        for (int u = 0; u < MM; u++)
            sc += ftanh(sh_wq[u] + uh[(size_t)u * TT]) * sh_vd[u];
    }
    sh_red[tid] = (tid < TT) ? sc : -1e30f;
    __syncthreads();
    for (int off = 128; off > 0; off >>= 1) {
        if (tid < off) sh_red[tid] = fmaxf(sh_red[tid], sh_red[tid + off]);
        __syncthreads();
    }
    float mx = sh_red[0];
    __syncthreads();
    float e = (tid < TT) ? __expf(sc - mx) : 0.f;
    sh_red[tid] = e;
    __syncthreads();
    for (int off = 128; off > 0; off >>= 1) {
        if (tid < off) sh_red[tid] += sh_red[tid + off];
        __syncthreads();
    }
    float ssum = sh_red[0];
    __syncthreads();
    if (tid < TT) sh_beta[tid] = __fdividef(e, ssum);
    __syncthreads();

    // ctx[m=tid] = sum_t beta[t] * H[b][t][m]
    float ctx = 0.f;
    {
        const float* hrow = g_H + (size_t)b * TT * MM + tid;
#pragma unroll 4
        for (int t2 = 0; t2 < TT; t2++) ctx += sh_beta[t2] * hrow[(size_t)t2 * MM];
    }

    if (!final_mode) {
        sh_red[tid] = ctx * wt_w[1 + tid];
        __syncthreads();
        for (int off = 128; off > 0; off >>= 1) {
            if (tid < off) sh_red[tid] += sh_red[tid + off];
            __syncthreads();
        }
        if (tid == 0) {
            float y = dec_data[(size_t)b * TT + step];
            g_yt[b] = sh_red[0] + y * wt_w[0] + wt_b[0];
        }
        return;
    }

    // final head: v = [d | ctx];  out[b] = relu(v @ l1^T + b1) @ l2^T + b2
    sh_v[tid] = g_d[p][b * PP + tid];
    sh_v[256 + tid] = ctx;
    __syncthreads();
    float a = l1_b[tid];
    const float* w = l1_w + tid * 512;
#pragma unroll 8
    for (int k = 0; k < 512; k++) a += sh_v[k] * w[k];
    a = fmaxf(a, 0.f);
    sh_red[tid] = a * l2_w[tid];
    __syncthreads();
    for (int off = 128; off > 0; off >>= 1) {
        if (tid < off) sh_red[tid] += sh_red[tid + off];
        __syncthreads();
    }
    if (tid == 0) out[b] = sh_red[0] + l2_b[0];
}

// ---------------- decoder LSTM gates GEMM + fused activation -----------------
__global__ __launch_bounds__(256) void dec_gates_act_kernel(
    const float* __restrict__ Wih, const float* __restrict__ Whh,
    const float* __restrict__ bih, const float* __restrict__ bhh, int p)
{
    __shared__ float As[16][65];
    __shared__ float Bs[16][68];
    __shared__ float Sg[64][68];
    const int j0 = blockIdx.x * 16;
    const int b0 = blockIdx.y * 64;
    const int tid = threadIdx.x;
    const int tx = tid & 15, ty = tid >> 4;
    float acc[4][4];
#pragma unroll
    for (int i = 0; i < 4; i++)
#pragma unroll
        for (int j = 0; j < 4; j++) acc[i][j] = 0.f;

    const float* d_in = g_d[p];
    const float* s_in = g_s[p];
    float* d_out = g_d[p ^ 1];
    float* s_out = g_s[p ^ 1];

    for (int k0 = 0; k0 < PP; k0 += 16) {
#pragma unroll
        for (int i = 0; i < 4; i++) {
            int idx = tid + i * 256;
            int c = idx >> 4, k = idx & 15;
            As[k][c] = d_in[(b0 + c) * PP + (k0 + k)];
            int gate = c >> 4, jj = c & 15;
            Bs[k][c] = Whh[(gate * 256 + j0 + jj) * PP + (k0 + k)];
        }
        __syncthreads();
#pragma unroll
        for (int kk = 0; kk < 16; kk++) {
            float a[4], bv[4];
#pragma unroll
            for (int i = 0; i < 4; i++) a[i] = As[kk][ty * 4 + i];
#pragma unroll
            for (int j = 0; j < 4; j++) bv[j] = Bs[kk][tx * 4 + j];
#pragma unroll
            for (int i = 0; i < 4; i++)
#pragma unroll
                for (int j = 0; j < 4; j++) acc[i][j] += a[i] * bv[j];
        }
        __syncthreads();
    }
#pragma unroll
    for (int i = 0; i < 4; i++)
#pragma unroll
        for (int j = 0; j < 4; j++)
            Sg[ty * 4 + i][tx * 4 + j] = acc[i][j];
    __syncthreads();

#pragma unroll
    for (int i = 0; i < 4; i++) {
        int idx = tid + i * 256;
        int r = idx >> 4, jj = idx & 15;
        int col0 = j0 + jj;
        int b = b0 + r;
        float yt = g_yt[b];
        float gi = Sg[r][jj]      + yt * Wih[col0]       + bih[col0]       + bhh[col0];
        float gf = Sg[r][16 + jj] + yt * Wih[256 + col0] + bih[256 + col0] + bhh[256 + col0];
        float gg = Sg[r][32 + jj] + yt * Wih[512 + col0] + bih[512 + col0] + bhh[512 + col0];
        float go = Sg[r][48 + jj] + yt * Wih[768 + col0] + bih[768 + col0] + bhh[768 + col0];
        int sidx = b * PP + col0;
        float s_old = s_in[sidx];
        float sn = fsig(gf) * s_old + fsig(gi) * ftanh(gg);
        float dn = fsig(go) * ftanh(sn);
        s_out[sidx] = sn;
        d_out[sidx] = dn;
    }
}

// ---------------- launch -----------------------------------------------------
extern "C" void kernel_launch(void* const* d_in, const int* in_sizes, int n_in,
                              void* d_out, int out_size)
{
    const float* enc_data = (const float*)d_in[0];
    const float* dec_data = (const float*)d_in[1];
    const float* enc_Wih  = (const float*)d_in[2];
    const float* enc_Whh  = (const float*)d_in[3];
    const float* enc_bih  = (const float*)d_in[4];
    const float* enc_bhh  = (const float*)d_in[5];
    const float* We       = (const float*)d_in[6];
    const float* Ue       = (const float*)d_in[7];
    const float* ve       = (const float*)d_in[8];
    const float* Wd       = (const float*)d_in[9];
    const float* Ud       = (const float*)d_in[10];
    const float* vd       = (const float*)d_in[11];
    const float* wt_w     = (const float*)d_in[12];
    const float* wt_b     = (const float*)d_in[13];
    const float* dec_Wih  = (const float*)d_in[14];
    const float* dec_Whh  = (const float*)d_in[15];
    const float* dec_bih  = (const float*)d_in[16];
    const float* dec_bhh  = (const float*)d_in[17];
    const float* l1_w     = (const float*)d_in[18];
    const float* l1_b     = (const float*)d_in[19];
    const float* l2_w     = (const float*)d_in[20];
    const float* l2_b     = (const float*)d_in[21];
    float* out = (float*)d_out;

    ue_pre_kernel<<<dim3(NN / 64, TT / 64, BB), 256>>>(enc_data, Ue);

    for (int t = 0; t < TT; t++) {
        int p = t & 1;
        enc_wq_kernel<<<dim3(TT / 64, BB / 64), 256>>>(We, p);
        enc_attn_kernel<<<BB, 128>>>(enc_data, ve, t);
        enc_gates_act_kernel<<<dim3(16, 16), 256>>>(enc_Wih, enc_Whh, enc_bih, enc_bhh, t, p);
    }

    uh_pre_kernel<<<dim3(TT / 64, MM / 64, BB), 256>>>(Ud);

    for (int step = 0; step < TT - 1; step++) {
        int p = step & 1;
        dec_wq_kernel<<<dim3(MM / 64, BB / 64), 256>>>(Wd, p);
        dec_attn_kernel<<<BB, 256>>>(dec_data, vd, wt_w, wt_b, step, 0, p,
                                     l1_w, l1_b, l2_w, l2_b, out);
        dec_gates_act_kernel<<<dim3(16, 16), 256>>>(dec_Wih, dec_Whh, dec_bih, dec_bhh, p);
    }

    // final attention + head with last decoder state (parity 127&1 = 1)
    dec_wq_kernel<<<dim3(MM / 64, BB / 64), 256>>>(Wd, 1);
    dec_attn_kernel<<<BB, 256>>>(dec_data, vd, wt_w, wt_b, 0, 1, 1,
                                 l1_w, l1_b, l2_w, l2_b, out);
}